// round 9
// baseline (speedup 1.0000x reference)
#include <cuda_runtime.h>
#include <cstddef>

#define NMAX     400000
#define FDIM     128
#define KNBR     5
#define NUPMAX   100000
#define CAP      32            // per-dest bin capacity (in-degree ~ Poisson(5))
#define MAXSPILL 8192          // provable-correctness overflow path

// Scratch (static device allocations):
//   g_map[i]  : 0 = dead dest; -1 = transient mark; else compact_id + 1
//   g_deg     : live in-degree per compact id (atomic cursor during fill)
//   g_edges   : fixed bins [cid][CAP] of (src, weight-bits)
__device__ int   g_map[NMAX];
__device__ int   g_cnt;
__device__ int   g_deg[NUPMAX];
__device__ int2  g_edges[(size_t)NUPMAX * CAP];
__device__ int   g_spillcnt;
__device__ int3  g_spill[MAXSPILL];   // (cid, src, weight-bits)

// ---------------------------------------------------------------------------
// 0: clear map + degree cursors + counters (vectorized)
// ---------------------------------------------------------------------------
__global__ void clear_kernel() {
    const int i = blockIdx.x * blockDim.x + threadIdx.x;
    if (i == 0) { g_cnt = 0; g_spillcnt = 0; }
    const int4 z = make_int4(0, 0, 0, 0);
    if (i < NMAX / 4)   reinterpret_cast<int4*>(g_map)[i] = z;
    if (i < NUPMAX / 4) reinterpret_cast<int4*>(g_deg)[i] = z;
}

// ---------------------------------------------------------------------------
// 1: fused mark + compact-id assign. CAS winner assigns the id.
// ---------------------------------------------------------------------------
__global__ void mark_assign_kernel(const int* __restrict__ sel_idx, int n_up) {
    const int j = blockIdx.x * blockDim.x + threadIdx.x;
    if (j >= n_up) return;
    const int idx = sel_idx[j];
    if (atomicCAS(&g_map[idx], 0, -1) == 0)
        g_map[idx] = atomicAdd(&g_cnt, 1) + 1;
}

// ---------------------------------------------------------------------------
// 2: fill fixed-capacity bins; 4 edges per thread for MLP on the random
//    map lookups.
// ---------------------------------------------------------------------------
__global__ void fill_kernel(const int*   __restrict__ nidx,
                            const float* __restrict__ weights,
                            int n_edge, int K) {
    const int t = blockIdx.x * blockDim.x + threadIdx.x;
    const int n4 = n_edge >> 2;
    if (t >= n4) return;

    const int4   i4 = reinterpret_cast<const int4*>(nidx)[t];
    const float4 w4 = reinterpret_cast<const float4*>(weights)[t];
    const int e0 = t * 4;
    int   idx[4] = { i4.x, i4.y, i4.z, i4.w };
    float w[4]   = { w4.x, w4.y, w4.z, w4.w };

    int m[4];
#pragma unroll
    for (int k = 0; k < 4; ++k)                   // 4 independent L2 lookups
        m[k] = (idx[k] >= 0) ? __ldg(&g_map[idx[k]]) : 0;

#pragma unroll
    for (int k = 0; k < 4; ++k) {
        if (m[k] > 0) {
            const int cid = m[k] - 1;
            const int pos = atomicAdd(&g_deg[cid], 1);
            const int src = (e0 + k) / K;
            const int wb  = __float_as_int(w[k]);
            if (pos < CAP) {
                g_edges[(size_t)cid * CAP + pos] = make_int2(src, wb);
            } else {                              // essentially never taken
                const int s = atomicAdd(&g_spillcnt, 1);
                if (s < MAXSPILL) g_spill[s] = make_int3(cid, src, wb);
            }
        }
    }
    // tail edges (n_edge % 4)
    if (t == 0) {
        for (int e = n4 * 4; e < n_edge; ++e) {
            const int idxe = nidx[e];
            if (idxe < 0) continue;
            const int me = g_map[idxe];
            if (me <= 0) continue;
            const int cid = me - 1;
            const int pos = atomicAdd(&g_deg[cid], 1);
            const int wb  = __float_as_int(weights[e]);
            if (pos < CAP) g_edges[(size_t)cid * CAP + pos] = make_int2(e / K, wb);
            else { const int s = atomicAdd(&g_spillcnt, 1);
                   if (s < MAXSPILL) g_spill[s] = make_int3(cid, e / K, wb); }
        }
    }
}

// ---------------------------------------------------------------------------
// 3: fused consume + gather. One warp per OUTPUT row j.
//    Edge loop runs in batches of 8: all 8 independent 512B feature loads
//    issued before any accumulation -> per-warp MLP ~8 (latency hiding).
//    92% of rows (deg<=8) finish in a single batch.
// ---------------------------------------------------------------------------
__global__ void consume_gather_kernel(const float* __restrict__ features,
                                      const int*   __restrict__ sel_idx,
                                      float* __restrict__ out, int n_up) {
    const int j    = (blockIdx.x * blockDim.x + threadIdx.x) >> 5;
    const int lane = threadIdx.x & 31;
    if (j >= n_up) return;

    const int cid = g_map[sel_idx[j]] - 1;        // sel rows always mapped
    const int deg = g_deg[cid];
    const int m   = min(deg, CAP);

    int2 rec = make_int2(0, 0);
    if (lane < m) rec = g_edges[(size_t)cid * CAP + lane];

    float4 acc  = make_float4(0.f, 0.f, 0.f, 0.f);
    float  wsum = 0.f;
    const float4* feat4 = reinterpret_cast<const float4*>(features);

    for (int base = 0; base < m; base += 8) {
        const int cnt = min(8, m - base);
        float4 f[8];
        float  w[8];
        // Phase A: shuffle metadata + issue ALL loads (independent, in flight)
#pragma unroll
        for (int k = 0; k < 8; ++k) {
            if (k < cnt) {
                const int s = __shfl_sync(0xFFFFFFFFu, rec.x, base + k);
                w[k] = __int_as_float(__shfl_sync(0xFFFFFFFFu, rec.y, base + k));
                f[k] = feat4[(size_t)s * 32 + lane];
            }
        }
        // Phase B: accumulate
#pragma unroll
        for (int k = 0; k < 8; ++k) {
            if (k < cnt) {
                acc.x += w[k] * f[k].x; acc.y += w[k] * f[k].y;
                acc.z += w[k] * f[k].z; acc.w += w[k] * f[k].w;
                wsum  += w[k];
            }
        }
    }

    if (deg > CAP) {                              // correctness backstop
        const int nsp = min(g_spillcnt, MAXSPILL);
        for (int s = 0; s < nsp; ++s) {
            const int3 r = g_spill[s];
            if (r.x == cid) {
                const float w = __int_as_float(r.z);
                const float4 f = feat4[(size_t)r.y * 32 + lane];
                acc.x += w * f.x; acc.y += w * f.y; acc.z += w * f.z; acc.w += w * f.w;
                wsum += w;
            }
        }
    }

    const float ws  = (wsum > 0.f) ? wsum : 0.001f;
    const float inv = 1.0f / ws;
    reinterpret_cast<float4*>(out)[(size_t)j * 32 + lane] =
        make_float4(acc.x * inv, acc.y * inv, acc.z * inv, acc.w * inv);
}

// ---------------------------------------------------------------------------
// Launch
// Inputs: features [N,128] f32, weights_down [N,5] f32,
//         nidx_down [N,5] i32, sel_idx_up [N_UP,1] i32 -> out [N_UP,128] f32
// ---------------------------------------------------------------------------
extern "C" void kernel_launch(void* const* d_in, const int* in_sizes, int n_in,
                              void* d_out, int out_size) {
    const float* features = (const float*)d_in[0];
    const float* weights  = (const float*)d_in[1];
    const int*   nidx     = (const int*)  d_in[2];
    const int*   sel_idx  = (const int*)  d_in[3];
    float*       out      = (float*)d_out;

    const int N      = in_sizes[0] / FDIM;
    const int N_UP   = in_sizes[3];
    const int n_edge = in_sizes[2];
    const int K      = n_edge / N;

    clear_kernel<<<(NMAX / 4 + 255) / 256, 256>>>();
    mark_assign_kernel<<<(N_UP + 255) / 256, 256>>>(sel_idx, N_UP);
    fill_kernel<<<(n_edge / 4 + 255) / 256, 256>>>(nidx, weights, n_edge, K);

    const int WPB = 8;                            // 8 warps / 256-thread block
    consume_gather_kernel<<<(N_UP + WPB - 1) / WPB, WPB * 32>>>(features, sel_idx,
                                                                out, N_UP);
}

// round 13
// speedup vs baseline: 1.6456x; 1.6456x over previous
#include <cuda_runtime.h>
#include <cstddef>

#define NMAX     400000
#define FDIM     128
#define KNBR     5
#define NUPMAX   100000
#define CAP      32            // per-dest bin capacity (in-degree ~ Poisson(5))
#define MAXSPILL 8192          // provable-correctness overflow path

// Scratch (static device allocations):
//   g_map[i]   : 0 = dead dest; -1 = transient mark; else compact_id + 1
//   g_deg      : live in-degree per compact id (atomic cursor during fill)
//   g_edges    : fixed bins [cid][CAP] of (src, weight-bits)
//   g_resolve  : per-output-row (cid, deg) precomputed for coalesced access
__device__ int   g_map[NMAX];
__device__ int   g_cnt;
__device__ int   g_deg[NUPMAX];
__device__ int2  g_edges[(size_t)NUPMAX * CAP];
__device__ int2  g_resolve[NUPMAX];
__device__ int   g_spillcnt;
__device__ int3  g_spill[MAXSPILL];   // (cid, src, weight-bits)

// ---------------------------------------------------------------------------
// 0: clear map + degree cursors + counters (vectorized)
// ---------------------------------------------------------------------------
__global__ void clear_kernel() {
    const int i = blockIdx.x * blockDim.x + threadIdx.x;
    if (i == 0) { g_cnt = 0; g_spillcnt = 0; }
    const int4 z = make_int4(0, 0, 0, 0);
    if (i < NMAX / 4)   reinterpret_cast<int4*>(g_map)[i] = z;
    if (i < NUPMAX / 4) reinterpret_cast<int4*>(g_deg)[i] = z;
}

// ---------------------------------------------------------------------------
// 1: fused mark + compact-id assign. CAS winner assigns the id.
// ---------------------------------------------------------------------------
__global__ void mark_assign_kernel(const int* __restrict__ sel_idx, int n_up) {
    const int j = blockIdx.x * blockDim.x + threadIdx.x;
    if (j >= n_up) return;
    const int idx = sel_idx[j];
    if (atomicCAS(&g_map[idx], 0, -1) == 0)
        g_map[idx] = atomicAdd(&g_cnt, 1) + 1;
}

// ---------------------------------------------------------------------------
// 2: fill fixed-capacity bins; 4 edges per thread for MLP on the random
//    map lookups.
// ---------------------------------------------------------------------------
__global__ void fill_kernel(const int*   __restrict__ nidx,
                            const float* __restrict__ weights,
                            int n_edge, int K) {
    const int t = blockIdx.x * blockDim.x + threadIdx.x;
    const int n4 = n_edge >> 2;
    if (t >= n4) return;

    const int4   i4 = reinterpret_cast<const int4*>(nidx)[t];
    const float4 w4 = reinterpret_cast<const float4*>(weights)[t];
    const int e0 = t * 4;
    int   idx[4] = { i4.x, i4.y, i4.z, i4.w };
    float w[4]   = { w4.x, w4.y, w4.z, w4.w };

    int m[4];
#pragma unroll
    for (int k = 0; k < 4; ++k)                   // 4 independent L2 lookups
        m[k] = (idx[k] >= 0) ? __ldg(&g_map[idx[k]]) : 0;

#pragma unroll
    for (int k = 0; k < 4; ++k) {
        if (m[k] > 0) {
            const int cid = m[k] - 1;
            const int pos = atomicAdd(&g_deg[cid], 1);
            const int src = (e0 + k) / K;
            const int wb  = __float_as_int(w[k]);
            if (pos < CAP) {
                g_edges[(size_t)cid * CAP + pos] = make_int2(src, wb);
            } else {                              // essentially never taken
                const int s = atomicAdd(&g_spillcnt, 1);
                if (s < MAXSPILL) g_spill[s] = make_int3(cid, src, wb);
            }
        }
    }
    // tail edges (n_edge % 4)
    if (t == 0) {
        for (int e = n4 * 4; e < n_edge; ++e) {
            const int idxe = nidx[e];
            if (idxe < 0) continue;
            const int me = g_map[idxe];
            if (me <= 0) continue;
            const int cid = me - 1;
            const int pos = atomicAdd(&g_deg[cid], 1);
            const int wb  = __float_as_int(weights[e]);
            if (pos < CAP) g_edges[(size_t)cid * CAP + pos] = make_int2(e / K, wb);
            else { const int s = atomicAdd(&g_spillcnt, 1);
                   if (s < MAXSPILL) g_spill[s] = make_int3(cid, e / K, wb); }
        }
    }
}

// ---------------------------------------------------------------------------
// 3: resolve. Precompute (cid, deg) per output row so consume's dependent
//    chain shrinks from 4 random hops to: coalesced resolve -> bin -> feat.
//    One thread per row; huge thread-level MLP hides the 2 random loads.
// ---------------------------------------------------------------------------
__global__ void resolve_kernel(const int* __restrict__ sel_idx, int n_up) {
    const int j = blockIdx.x * blockDim.x + threadIdx.x;
    if (j >= n_up) return;
    const int cid = g_map[sel_idx[j]] - 1;        // sel rows always mapped
    g_resolve[j] = make_int2(cid, g_deg[cid]);
}

// ---------------------------------------------------------------------------
// 4: fused consume + gather. One warp per OUTPUT row j.
//    R8-proven unroll-4 body (36 regs); prologue is now one coalesced 8B
//    read plus the bin load.
// ---------------------------------------------------------------------------
__global__ void __launch_bounds__(256, 6)
consume_gather_kernel(const float* __restrict__ features,
                      float* __restrict__ out, int n_up) {
    const int j    = (blockIdx.x * blockDim.x + threadIdx.x) >> 5;
    const int lane = threadIdx.x & 31;
    if (j >= n_up) return;

    const int2 rs  = g_resolve[j];                // coalesced (warp-broadcast)
    const int  cid = rs.x;
    const int  deg = rs.y;
    const int  m   = min(deg, CAP);

    int2 rec = make_int2(0, 0);
    if (lane < m) rec = g_edges[(size_t)cid * CAP + lane];

    float4 acc  = make_float4(0.f, 0.f, 0.f, 0.f);
    float  wsum = 0.f;
    const float4* feat4 = reinterpret_cast<const float4*>(features);

    int e = 0;
    for (; e + 4 <= m; e += 4) {
        const int s0 = __shfl_sync(0xFFFFFFFFu, rec.x, e);
        const int s1 = __shfl_sync(0xFFFFFFFFu, rec.x, e + 1);
        const int s2 = __shfl_sync(0xFFFFFFFFu, rec.x, e + 2);
        const int s3 = __shfl_sync(0xFFFFFFFFu, rec.x, e + 3);
        const float w0 = __int_as_float(__shfl_sync(0xFFFFFFFFu, rec.y, e));
        const float w1 = __int_as_float(__shfl_sync(0xFFFFFFFFu, rec.y, e + 1));
        const float w2 = __int_as_float(__shfl_sync(0xFFFFFFFFu, rec.y, e + 2));
        const float w3 = __int_as_float(__shfl_sync(0xFFFFFFFFu, rec.y, e + 3));
        const float4 f0 = feat4[(size_t)s0 * 32 + lane];   // 4 loads in flight
        const float4 f1 = feat4[(size_t)s1 * 32 + lane];
        const float4 f2 = feat4[(size_t)s2 * 32 + lane];
        const float4 f3 = feat4[(size_t)s3 * 32 + lane];
        acc.x += w0 * f0.x; acc.y += w0 * f0.y; acc.z += w0 * f0.z; acc.w += w0 * f0.w;
        acc.x += w1 * f1.x; acc.y += w1 * f1.y; acc.z += w1 * f1.z; acc.w += w1 * f1.w;
        acc.x += w2 * f2.x; acc.y += w2 * f2.y; acc.z += w2 * f2.z; acc.w += w2 * f2.w;
        acc.x += w3 * f3.x; acc.y += w3 * f3.y; acc.z += w3 * f3.z; acc.w += w3 * f3.w;
        wsum += w0 + w1 + w2 + w3;
    }
    for (; e < m; ++e) {
        const int   s = __shfl_sync(0xFFFFFFFFu, rec.x, e);
        const float w = __int_as_float(__shfl_sync(0xFFFFFFFFu, rec.y, e));
        const float4 f = feat4[(size_t)s * 32 + lane];
        acc.x += w * f.x; acc.y += w * f.y; acc.z += w * f.z; acc.w += w * f.w;
        wsum += w;
    }

    if (deg > CAP) {                              // correctness backstop
        const int nsp = min(g_spillcnt, MAXSPILL);
        for (int s = 0; s < nsp; ++s) {
            const int3 r = g_spill[s];
            if (r.x == cid) {
                const float w = __int_as_float(r.z);
                const float4 f = feat4[(size_t)r.y * 32 + lane];
                acc.x += w * f.x; acc.y += w * f.y; acc.z += w * f.z; acc.w += w * f.w;
                wsum += w;
            }
        }
    }

    const float ws  = (wsum > 0.f) ? wsum : 0.001f;
    const float inv = 1.0f / ws;
    reinterpret_cast<float4*>(out)[(size_t)j * 32 + lane] =
        make_float4(acc.x * inv, acc.y * inv, acc.z * inv, acc.w * inv);
}

// ---------------------------------------------------------------------------
// Launch
// Inputs: features [N,128] f32, weights_down [N,5] f32,
//         nidx_down [N,5] i32, sel_idx_up [N_UP,1] i32 -> out [N_UP,128] f32
// ---------------------------------------------------------------------------
extern "C" void kernel_launch(void* const* d_in, const int* in_sizes, int n_in,
                              void* d_out, int out_size) {
    const float* features = (const float*)d_in[0];
    const float* weights  = (const float*)d_in[1];
    const int*   nidx     = (const int*)  d_in[2];
    const int*   sel_idx  = (const int*)  d_in[3];
    float*       out      = (float*)d_out;

    const int N      = in_sizes[0] / FDIM;
    const int N_UP   = in_sizes[3];
    const int n_edge = in_sizes[2];
    const int K      = n_edge / N;

    clear_kernel<<<(NMAX / 4 + 255) / 256, 256>>>();
    mark_assign_kernel<<<(N_UP + 255) / 256, 256>>>(sel_idx, N_UP);
    fill_kernel<<<(n_edge / 4 + 255) / 256, 256>>>(nidx, weights, n_edge, K);
    resolve_kernel<<<(N_UP + 255) / 256, 256>>>(sel_idx, N_UP);

    const int WPB = 8;                            // 8 warps / 256-thread block
    consume_gather_kernel<<<(N_UP + WPB - 1) / WPB, WPB * 32>>>(features, out, N_UP);
}